// round 15
// baseline (speedup 1.0000x reference)
#include <cuda_runtime.h>
#include <cstdint>

// Problem dims (fixed)
#define ZD 16
#define YD 384
#define XD 384
#define YP 386        // padded y rows (row 0 and 385 stay zero)
#define NWIN_I 17     // z-pairs
#define NWIN_Y 385    // window rows
#define NGX 48        // 8-window groups; group 47 also does edge window x=384
#define TOTAL_B_THREADS (NWIN_I * NWIN_Y * NGX)          // 314160
#define K2_BLK 256
#define B_BLOCKS ((TOTAL_B_THREADS + K2_BLK - 1) / K2_BLK)   // 1228
#define NP_WIN 148225.0                                   // 385*385
#define SLAB (YD * XD)                                    // 147456
#define LUT_STRIDE 257                                    // 257 % 32 == 1 -> bank = (copy+idx)%32
#define LUT_COPIES 16

// Scratch (static __device__ — zero-initialized; padded rows never written)
__device__ float         g_E[NWIN_I * YP * XD];   // z-pair sums of (s-l)^2
__device__ unsigned char g_ZC[NWIN_I * YP * XD];  // z-pair code: l0@0,l1@2,p0@4,p1@6
__device__ float2        g_S[NWIN_I * YP * XD];   // z-pair sums of (softplus(p), softplus(-p))
__device__ float         g_part[3 * B_BLOCKS];
__device__ unsigned      g_count;

// ---------------------------------------------------------------------------
// k1: z-pass. One thread per (y,x) column; walks z, emits 17 z-pair
// (E, code, softplus-pair) records.  (identical to R12/R14 proven k1)
__global__ void k1(const float* __restrict__ pred, const int* __restrict__ lab) {
    int x = threadIdx.x;
    int y = blockIdx.x;
    if (x == 0 && y == 0) g_count = 0u;
    int base = y * XD + x;
    int obase = (y + 1) * XD + x;   // padded row index

    float dprev = 0.f, spPrev = 0.f, snPrev = 0.f;
    unsigned cprev = 0u;
#pragma unroll 4
    for (int z = 0; z < ZD; z++) {
        float p = __ldg(&pred[z * SLAB + base]);
        int   l = __ldg(&lab[z * SLAB + base]);
        float s = __fdividef(1.f, 1.f + __expf(-p));
        float f = (float)l;
        float d = (s - f) * (s - f);
        float sp = fmaxf(p, 0.f) + __logf(1.f + __expf(-fabsf(p)));  // softplus(p)
        float sn = sp - p;                                           // softplus(-p)
        unsigned c = (unsigned)(l & 1) | (p > 0.f ? 0x10u : 0u);  // lab@0, pred@4
        int o = z * (YP * XD) + obase;
        g_E[o]  = dprev + d;
        g_ZC[o] = (unsigned char)(cprev | (c << 2));
        g_S[o]  = make_float2(spPrev + sp, snPrev + sn);
        dprev = d; spPrev = sp; snPrev = sn;
        cprev = c;
    }
    int o = ZD * (YP * XD) + obase;
    g_E[o]  = dprev;
    g_ZC[o] = (unsigned char)cprev;
    g_S[o]  = make_float2(spPrev, snPrev);
}

// ---------------------------------------------------------------------------
__device__ __forceinline__ float warp_sum(float v) {
#pragma unroll
    for (int off = 16; off > 0; off >>= 1)
        v += __shfl_down_sync(0xffffffffu, v, off);
    return v;
}

// ---------------------------------------------------------------------------
// k2: each thread sweeps 8 consecutive windows along x for a fixed (i, yw).
// LUT is replicated 16x (stride 257) so the data-dependent lookups are
// bank-conflict-free: lane l uses copy (l & 15).
__global__ void __launch_bounds__(K2_BLK, 8)
k2(const float* __restrict__ area, float* __restrict__ out) {
    __shared__ float a_sh[LUT_COPIES * LUT_STRIDE];
    __shared__ float wN[8], wD[8], wB[8];
    __shared__ bool is_last;
    int tid = threadIdx.x;

    // permuted area LUT copy 0: index = (leftcol_nibble<<4)|rightcol_nibble,
    // nibble bit m = dz*2+dy -> true byte bit 2m+dx (left dx=0, right dx=1)
    {
        int a = tid >> 4, b = tid & 15;
        int byte = 0;
#pragma unroll
        for (int m = 0; m < 4; m++) {
            byte |= ((a >> m) & 1) << (2 * m);
            byte |= ((b >> m) & 1) << (2 * m + 1);
        }
        a_sh[tid] = __ldg(&area[byte]);
    }
    __syncthreads();
    // replicate to copies 1..15
    {
        float v = a_sh[tid];
#pragma unroll
        for (int c = 1; c < LUT_COPIES; c++)
            a_sh[c * LUT_STRIDE + tid] = v;
    }
    __syncthreads();
    const float* lut = a_sh + (tid & 15) * LUT_STRIDE;

    float S1 = 0.f, S2 = 0.f, Sq = 0.f, accB = 0.f;
    int t = blockIdx.x * K2_BLK + tid;
    bool valid = (t < TOTAL_B_THREADS);

    int g = 0, yw = 0, i = 0, x0 = 0, rA = 0, rB = 0;
    float4 a0, a1, b0, b1;
    a0 = a1 = b0 = b1 = make_float4(0.f, 0.f, 0.f, 0.f);
    uint2 za = make_uint2(0u, 0u), zb = za;
    if (valid) {
        g = t % NGX;
        int rem = t / NGX;
        yw = rem % NWIN_Y;
        i = rem / NWIN_Y;
        x0 = g * 8;
        rA = (i * YP + yw) * XD;
        rB = rA + XD;

        const float4* pA = reinterpret_cast<const float4*>(g_E + rA + x0);
        const float4* pB = reinterpret_cast<const float4*>(g_E + rB + x0);
        a0 = pA[0]; a1 = pA[1];
        b0 = pB[0]; b1 = pB[1];
        za = *reinterpret_cast<const uint2*>(g_ZC + rA + x0);
        zb = *reinterpret_cast<const uint2*>(g_ZC + rB + x0);
    }

    // my last column (feeds next lane's carry)
    float myLastF = a1.w + b1.w;
    unsigned myLastC = (za.y | (zb.y << 1)) >> 24;
    float upF = __shfl_up_sync(0xffffffffu, myLastF, 1);
    unsigned upC = __shfl_up_sync(0xffffffffu, myLastC, 1);

    if (valid) {
        float Fp;
        unsigned cbp;
        int lane = tid & 31;
        if (g == 0) {
            Fp = 0.f;
            cbp = 0u;
        } else if (lane == 0) {
            int c = x0 - 1;
            Fp = g_E[rA + c] + g_E[rB + c];
            cbp = (unsigned)g_ZC[rA + c] | ((unsigned)g_ZC[rB + c] << 1);
        } else {
            Fp = upF;
            cbp = upC;
        }

#pragma unroll
        for (int j = 0; j < 2; j++) {
            float4 ea = j ? a1 : a0;
            float4 eb = j ? b1 : b0;
            // column codes for 4 columns: zc bytes <= 0x55 -> <<1 stays in-lane
            unsigned cw = (j ? za.y : za.x) | ((j ? zb.y : zb.x) << 1);
            // prevw byte k = code of column k-1 (byte0 = carry)
            unsigned prevw = __byte_perm(cw, cbp, 0x2104);
            // L byte k = lidx of window k ; P byte k = pidx of window k
            unsigned L = ((prevw << 4) & 0xF0F0F0F0u) | (cw & 0x0F0F0F0Fu);
            unsigned P = (prevw & 0xF0F0F0F0u) | ((cw >> 4) & 0x0F0F0F0Fu);

            float F0 = ea.x + eb.x;
            float F1 = ea.y + eb.y;
            float F2 = ea.z + eb.z;
            float F3 = ea.w + eb.w;

            float q0 = Fp + F0;
            float q1 = F0 + F1;
            float q2 = F1 + F2;
            float q3 = F2 + F3;

            float la0 = lut[L & 0xFFu];
            float la1 = lut[(L >> 8) & 0xFFu];
            float la2 = lut[(L >> 16) & 0xFFu];
            float la3 = lut[L >> 24];
            float pa0 = lut[P & 0xFFu];
            float pa1 = lut[(P >> 8) & 0xFFu];
            float pa2 = lut[(P >> 16) & 0xFFu];
            float pa3 = lut[P >> 24];

            Sq = fmaf(q0, la0, Sq);
            Sq = fmaf(q1, la1, Sq);
            Sq = fmaf(q2, la2, Sq);
            Sq = fmaf(q3, la3, Sq);
            S1 += (la0 + la1) + (la2 + la3);
            S2 += (pa0 + pa1) + (pa2 + pa3);

            // rare path: window label byte 0 -> sum softplus(p); 255 -> softplus(-p)
            unsigned r = __vcmpeq4(L, 0u) | __vcmpeq4(L, 0xFFFFFFFFu);
            if (r) {
#pragma unroll
                for (int k = 0; k < 4; k++) {
                    unsigned lb = (L >> (8 * k)) & 0xFFu;
                    if (lb == 0u || lb == 255u) {
                        int x = x0 + 4 * j + k;     // window; cols x-1, x
                        float2 sRA = g_S[rA + x];
                        float2 sRB = g_S[rB + x];
                        float s0 = sRA.x + sRB.x;
                        float s1 = sRA.y + sRB.y;
                        if (x > 0) {
                            float2 sLA = g_S[rA + x - 1];
                            float2 sLB = g_S[rB + x - 1];
                            s0 += sLA.x + sLB.x;
                            s1 += sLA.y + sLB.y;
                        }
                        accB += (lb == 255u) ? s1 : s0;
                    }
                }
            }

            Fp = F3;
            cbp = cw >> 24;
        }

        // group 47: edge window x=384 (right column is zero padding)
        if (g == NGX - 1) {
            float q = Fp;
            unsigned lidx = (cbp << 4) & 0xF0u;
            unsigned pidx = cbp & 0xF0u;
            float la = lut[lidx];
            float pa = lut[pidx];
            Sq = fmaf(q, la, Sq);
            S1 += la;
            S2 += pa;
            if (lidx == 0u) {   // lidx==255 impossible here (low nibble is 0)
                float2 sLA = g_S[rA + 383];
                float2 sLB = g_S[rB + 383];
                accB += sLA.x + sLB.x;
            }
        }
    }
    float accN = fmaf(Sq, -0.125f, S1);   // sum of (1 - q/8)*la
    float accD = S1 + S2;

    // deterministic warp-shuffle reduction
    accN = warp_sum(accN);
    accD = warp_sum(accD);
    accB = warp_sum(accB);
    int lane = tid & 31, warp = tid >> 5;
    if (lane == 0) { wN[warp] = accN; wD[warp] = accD; wB[warp] = accB; }
    __syncthreads();
    if (warp == 0) {
        float vN = lane < 8 ? wN[lane] : 0.f;
        float vD = lane < 8 ? wD[lane] : 0.f;
        float vB = lane < 8 ? wB[lane] : 0.f;
#pragma unroll
        for (int off = 4; off > 0; off >>= 1) {
            vN += __shfl_down_sync(0xffffffffu, vN, off);
            vD += __shfl_down_sync(0xffffffffu, vD, off);
            vB += __shfl_down_sync(0xffffffffu, vB, off);
        }
        if (lane == 0) {
            g_part[3 * blockIdx.x + 0] = vN;
            g_part[3 * blockIdx.x + 1] = vD;
            g_part[3 * blockIdx.x + 2] = vB;
        }
    }

    __threadfence();
    if (tid == 0) {
        unsigned prev = atomicAdd(&g_count, 1u);
        is_last = (prev == B_BLOCKS - 1);
    }
    __syncthreads();
    if (!is_last) return;

    double sN = 0.0, sD = 0.0, sB = 0.0;
    for (int b = tid; b < B_BLOCKS; b += K2_BLK) {
        sN += (double)g_part[3 * b + 0];
        sD += (double)g_part[3 * b + 1];
        sB += (double)g_part[3 * b + 2];
    }
    __shared__ double rd[K2_BLK];
    rd[tid] = sN; __syncthreads();
    for (int s = K2_BLK / 2; s > 0; s >>= 1) { if (tid < s) rd[tid] += rd[tid + s]; __syncthreads(); }
    double tN = rd[0]; __syncthreads();
    rd[tid] = sD; __syncthreads();
    for (int s = K2_BLK / 2; s > 0; s >>= 1) { if (tid < s) rd[tid] += rd[tid + s]; __syncthreads(); }
    double tD = rd[0]; __syncthreads();
    rd[tid] = sB; __syncthreads();
    for (int s = K2_BLK / 2; s > 0; s >>= 1) { if (tid < s) rd[tid] += rd[tid + s]; __syncthreads(); }
    double tB = rd[0];

    if (tid == 0) {
        double dice = 1.0 - (2.0 * tN + 1e-3) / (tD + 1e-3);
        double vol = tB / (8.0 * NP_WIN);
        out[0] = (float)(dice + vol);
    }
}

// ---------------------------------------------------------------------------
extern "C" void kernel_launch(void* const* d_in, const int* in_sizes, int n_in,
                              void* d_out, int out_size) {
    const float* pred   = (const float*)d_in[0];
    const int*   labels = (const int*)d_in[1];
    const float* area   = (const float*)d_in[2];

    k1<<<YD, XD>>>(pred, labels);
    k2<<<B_BLOCKS, K2_BLK>>>(area, (float*)d_out);
}

// round 16
// speedup vs baseline: 1.0571x; 1.0571x over previous
#include <cuda_runtime.h>
#include <cstdint>

// Problem dims (fixed)
#define ZD 16
#define YD 384
#define XD 384
#define YP 386        // padded y rows (row 0 and 385 stay zero)
#define NWIN_I 17     // z-pairs
#define NWIN_Y 385    // window rows
#define NGX 48        // 8-window groups; group 47 also does edge window x=384
#define TOTAL_B_THREADS (NWIN_I * NWIN_Y * NGX)          // 314160
#define K2_BLK 256
#define B_BLOCKS ((TOTAL_B_THREADS + K2_BLK - 1) / K2_BLK)   // 1228
#define NP_WIN 148225.0                                   // 385*385
#define SLAB (YD * XD)                                    // 147456

// Scratch (static __device__ — zero-initialized; padded rows never written)
__device__ float         g_E[NWIN_I * YP * XD];   // z-pair sums of (s-l)^2
__device__ unsigned char g_ZC[NWIN_I * YP * XD];  // z-pair code: l0@0,l1@2,p0@4,p1@6
__device__ float2        g_S[NWIN_I * YP * XD];   // z-pair sums of (softplus(p), softplus(-p))
__device__ float         g_part[3 * B_BLOCKS];
__device__ unsigned      g_count;

// ---------------------------------------------------------------------------
// k1: z-pass, split in half per column to halve the serial chain.
// grid (YD, 2): blockIdx.y==0 -> records 0..7 (z 0..7);
//               blockIdx.y==1 -> prologue z=7, records 8..16 (z 8..15 + tail).
__global__ void k1(const float* __restrict__ pred, const int* __restrict__ lab) {
    int x = threadIdx.x;
    int y = blockIdx.x;
    int h = blockIdx.y;
    if (x == 0 && y == 0 && h == 0) g_count = 0u;
    int base = y * XD + x;
    int obase = (y + 1) * XD + x;   // padded row index

    float dprev = 0.f, spPrev = 0.f, snPrev = 0.f;
    unsigned cprev = 0u;

    int zs = h ? 8 : 0;
    if (h) {
        // prologue: compute z=7 state (no write)
        float p = __ldg(&pred[7 * SLAB + base]);
        int   l = __ldg(&lab[7 * SLAB + base]);
        float s = __fdividef(1.f, 1.f + __expf(-p));
        float f = (float)l;
        dprev = (s - f) * (s - f);
        float sp = fmaxf(p, 0.f) + __logf(1.f + __expf(-fabsf(p)));
        spPrev = sp; snPrev = sp - p;
        cprev = (unsigned)(l & 1) | (p > 0.f ? 0x10u : 0u);
    }

#pragma unroll 4
    for (int z = zs; z < zs + 8; z++) {
        float p = __ldg(&pred[z * SLAB + base]);
        int   l = __ldg(&lab[z * SLAB + base]);
        float s = __fdividef(1.f, 1.f + __expf(-p));
        float f = (float)l;
        float d = (s - f) * (s - f);
        float sp = fmaxf(p, 0.f) + __logf(1.f + __expf(-fabsf(p)));  // softplus(p)
        float sn = sp - p;                                           // softplus(-p)
        unsigned c = (unsigned)(l & 1) | (p > 0.f ? 0x10u : 0u);  // lab@0, pred@4
        int o = z * (YP * XD) + obase;
        g_E[o]  = dprev + d;
        g_ZC[o] = (unsigned char)(cprev | (c << 2));
        g_S[o]  = make_float2(spPrev + sp, snPrev + sn);
        dprev = d; spPrev = sp; snPrev = sn;
        cprev = c;
    }
    if (h) {   // tail record i=16 (upper z is zero pad)
        int o = ZD * (YP * XD) + obase;
        g_E[o]  = dprev;
        g_ZC[o] = (unsigned char)cprev;
        g_S[o]  = make_float2(spPrev, snPrev);
    }
}

// ---------------------------------------------------------------------------
__device__ __forceinline__ float warp_sum(float v) {
#pragma unroll
    for (int off = 16; off > 0; off >>= 1)
        v += __shfl_down_sync(0xffffffffu, v, off);
    return v;
}

// ---------------------------------------------------------------------------
// k2: proven R14 form — each thread sweeps 8 consecutive windows along x for
// fixed (i, yw); carry via lane shuffle; direct 256-entry LUT. Global loads
// are issued before the LUT-build sync to overlap their latency.
__global__ void __launch_bounds__(K2_BLK, 8)
k2(const float* __restrict__ area, float* __restrict__ out) {
    __shared__ float a_sh[256];
    __shared__ float wN[8], wD[8], wB[8];
    __shared__ bool is_last;
    int tid = threadIdx.x;

    int t = blockIdx.x * K2_BLK + tid;
    bool valid = (t < TOTAL_B_THREADS);

    int g = 0, yw = 0, i = 0, x0 = 0, rA = 0, rB = 0;
    float4 a0, a1, b0, b1;
    a0 = a1 = b0 = b1 = make_float4(0.f, 0.f, 0.f, 0.f);
    uint2 za = make_uint2(0u, 0u), zb = za;
    if (valid) {
        g = t % NGX;
        int rem = t / NGX;
        yw = rem % NWIN_Y;
        i = rem / NWIN_Y;
        x0 = g * 8;
        rA = (i * YP + yw) * XD;
        rB = rA + XD;

        const float4* pA = reinterpret_cast<const float4*>(g_E + rA + x0);
        const float4* pB = reinterpret_cast<const float4*>(g_E + rB + x0);
        a0 = pA[0]; a1 = pA[1];
        b0 = pB[0]; b1 = pB[1];
        za = *reinterpret_cast<const uint2*>(g_ZC + rA + x0);
        zb = *reinterpret_cast<const uint2*>(g_ZC + rB + x0);
    }

    // permuted area LUT: index = (leftcol_nibble<<4)|rightcol_nibble,
    // nibble bit m = dz*2+dy -> true byte bit 2m+dx (left dx=0, right dx=1)
    {
        int a = tid >> 4, b = tid & 15;
        int byte = 0;
#pragma unroll
        for (int m = 0; m < 4; m++) {
            byte |= ((a >> m) & 1) << (2 * m);
            byte |= ((b >> m) & 1) << (2 * m + 1);
        }
        a_sh[tid] = __ldg(&area[byte]);
    }
    __syncthreads();

    // my last column (feeds next lane's carry)
    float myLastF = a1.w + b1.w;
    unsigned myLastC = (za.y | (zb.y << 1)) >> 24;
    float upF = __shfl_up_sync(0xffffffffu, myLastF, 1);
    unsigned upC = __shfl_up_sync(0xffffffffu, myLastC, 1);

    float S1 = 0.f, S2 = 0.f, Sq = 0.f, accB = 0.f;
    if (valid) {
        float Fp;
        unsigned cbp;
        int lane = tid & 31;
        if (g == 0) {
            Fp = 0.f;
            cbp = 0u;
        } else if (lane == 0) {
            int c = x0 - 1;
            Fp = g_E[rA + c] + g_E[rB + c];
            cbp = (unsigned)g_ZC[rA + c] | ((unsigned)g_ZC[rB + c] << 1);
        } else {
            Fp = upF;
            cbp = upC;
        }

#pragma unroll
        for (int j = 0; j < 2; j++) {
            float4 ea = j ? a1 : a0;
            float4 eb = j ? b1 : b0;
            // column codes for 4 columns: zc bytes <= 0x55 -> <<1 stays in-lane
            unsigned cw = (j ? za.y : za.x) | ((j ? zb.y : zb.x) << 1);
            // prevw byte k = code of column k-1 (byte0 = carry)
            unsigned prevw = __byte_perm(cw, cbp, 0x2104);
            // L byte k = lidx of window k ; P byte k = pidx of window k
            unsigned L = ((prevw << 4) & 0xF0F0F0F0u) | (cw & 0x0F0F0F0Fu);
            unsigned P = (prevw & 0xF0F0F0F0u) | ((cw >> 4) & 0x0F0F0F0Fu);

            float F0 = ea.x + eb.x;
            float F1 = ea.y + eb.y;
            float F2 = ea.z + eb.z;
            float F3 = ea.w + eb.w;

            float q0 = Fp + F0;
            float q1 = F0 + F1;
            float q2 = F1 + F2;
            float q3 = F2 + F3;

            float la0 = a_sh[L & 0xFFu];
            float la1 = a_sh[(L >> 8) & 0xFFu];
            float la2 = a_sh[(L >> 16) & 0xFFu];
            float la3 = a_sh[L >> 24];
            float pa0 = a_sh[P & 0xFFu];
            float pa1 = a_sh[(P >> 8) & 0xFFu];
            float pa2 = a_sh[(P >> 16) & 0xFFu];
            float pa3 = a_sh[P >> 24];

            Sq = fmaf(q0, la0, Sq);
            Sq = fmaf(q1, la1, Sq);
            Sq = fmaf(q2, la2, Sq);
            Sq = fmaf(q3, la3, Sq);
            S1 += (la0 + la1) + (la2 + la3);
            S2 += (pa0 + pa1) + (pa2 + pa3);

            // rare path: window label byte 0 -> sum softplus(p); 255 -> softplus(-p)
            unsigned r = __vcmpeq4(L, 0u) | __vcmpeq4(L, 0xFFFFFFFFu);
            if (r) {
#pragma unroll
                for (int k = 0; k < 4; k++) {
                    unsigned lb = (L >> (8 * k)) & 0xFFu;
                    if (lb == 0u || lb == 255u) {
                        int x = x0 + 4 * j + k;     // window; cols x-1, x
                        float2 sRA = g_S[rA + x];
                        float2 sRB = g_S[rB + x];
                        float s0 = sRA.x + sRB.x;
                        float s1 = sRA.y + sRB.y;
                        if (x > 0) {
                            float2 sLA = g_S[rA + x - 1];
                            float2 sLB = g_S[rB + x - 1];
                            s0 += sLA.x + sLB.x;
                            s1 += sLA.y + sLB.y;
                        }
                        accB += (lb == 255u) ? s1 : s0;
                    }
                }
            }

            Fp = F3;
            cbp = cw >> 24;
        }

        // group 47: edge window x=384 (right column is zero padding)
        if (g == NGX - 1) {
            float q = Fp;
            unsigned lidx = (cbp << 4) & 0xF0u;
            unsigned pidx = cbp & 0xF0u;
            float la = a_sh[lidx];
            float pa = a_sh[pidx];
            Sq = fmaf(q, la, Sq);
            S1 += la;
            S2 += pa;
            if (lidx == 0u) {   // lidx==255 impossible here (low nibble is 0)
                float2 sLA = g_S[rA + 383];
                float2 sLB = g_S[rB + 383];
                accB += sLA.x + sLB.x;
            }
        }
    }
    float accN = fmaf(Sq, -0.125f, S1);   // sum of (1 - q/8)*la
    float accD = S1 + S2;

    // deterministic warp-shuffle reduction
    accN = warp_sum(accN);
    accD = warp_sum(accD);
    accB = warp_sum(accB);
    int lane = tid & 31, warp = tid >> 5;
    if (lane == 0) { wN[warp] = accN; wD[warp] = accD; wB[warp] = accB; }
    __syncthreads();
    if (warp == 0) {
        float vN = lane < 8 ? wN[lane] : 0.f;
        float vD = lane < 8 ? wD[lane] : 0.f;
        float vB = lane < 8 ? wB[lane] : 0.f;
#pragma unroll
        for (int off = 4; off > 0; off >>= 1) {
            vN += __shfl_down_sync(0xffffffffu, vN, off);
            vD += __shfl_down_sync(0xffffffffu, vD, off);
            vB += __shfl_down_sync(0xffffffffu, vB, off);
        }
        if (lane == 0) {
            g_part[3 * blockIdx.x + 0] = vN;
            g_part[3 * blockIdx.x + 1] = vD;
            g_part[3 * blockIdx.x + 2] = vB;
        }
    }

    __threadfence();
    if (tid == 0) {
        unsigned prev = atomicAdd(&g_count, 1u);
        is_last = (prev == B_BLOCKS - 1);
    }
    __syncthreads();
    if (!is_last) return;

    double sN = 0.0, sD = 0.0, sB = 0.0;
    for (int b = tid; b < B_BLOCKS; b += K2_BLK) {
        sN += (double)g_part[3 * b + 0];
        sD += (double)g_part[3 * b + 1];
        sB += (double)g_part[3 * b + 2];
    }
    __shared__ double rd[K2_BLK];
    rd[tid] = sN; __syncthreads();
    for (int s = K2_BLK / 2; s > 0; s >>= 1) { if (tid < s) rd[tid] += rd[tid + s]; __syncthreads(); }
    double tN = rd[0]; __syncthreads();
    rd[tid] = sD; __syncthreads();
    for (int s = K2_BLK / 2; s > 0; s >>= 1) { if (tid < s) rd[tid] += rd[tid + s]; __syncthreads(); }
    double tD = rd[0]; __syncthreads();
    rd[tid] = sB; __syncthreads();
    for (int s = K2_BLK / 2; s > 0; s >>= 1) { if (tid < s) rd[tid] += rd[tid + s]; __syncthreads(); }
    double tB = rd[0];

    if (tid == 0) {
        double dice = 1.0 - (2.0 * tN + 1e-3) / (tD + 1e-3);
        double vol = tB / (8.0 * NP_WIN);
        out[0] = (float)(dice + vol);
    }
}

// ---------------------------------------------------------------------------
extern "C" void kernel_launch(void* const* d_in, const int* in_sizes, int n_in,
                              void* d_out, int out_size) {
    const float* pred   = (const float*)d_in[0];
    const int*   labels = (const int*)d_in[1];
    const float* area   = (const float*)d_in[2];

    dim3 g1(YD, 2);
    k1<<<g1, XD>>>(pred, labels);
    k2<<<B_BLOCKS, K2_BLK>>>(area, (float*)d_out);
}